// round 6
// baseline (speedup 1.0000x reference)
#include <cuda_runtime.h>

// Net0: x[B,2] -> fc1(2,7)+ELU -> 19x fc(7,7)+ELU -> fc(7,2) -> log_softmax.
// R6: 4 rows/thread, FFMA2 matmuls. Two algebraic folds make ELU 4 instr/half:
//   (1) carry g = elu(z)+1, fold the -1 into next bias:  b' = b - rowsum(W)
//   (2) fold log2e into W,b so the accumulator yields t = z*log2e directly:
//         g = ln2*max(t,0) + min(exp2(t), 1)
//       = FFMA-imm (rt1) + MUFU.EX2 + 2x FMNMX per scalar half.

constexpr int H       = 7;
constexpr int NMID    = 19;
constexpr int THREADS = 256;
constexpr int LSTRIDE = 56;   // float2 slots per layer: 7 i * (7 w + 1 bias)

typedef unsigned long long u64;

__device__ __forceinline__ u64 pack2(float lo, float hi) {
    u64 r; asm("mov.b64 %0, {%1, %2};" : "=l"(r) : "f"(lo), "f"(hi)); return r;
}
__device__ __forceinline__ void unpack2(u64 v, float& lo, float& hi) {
    asm("mov.b64 {%0, %1}, %2;" : "=f"(lo), "=f"(hi) : "l"(v));
}
__device__ __forceinline__ u64 fma2(u64 a, u64 b, u64 c) {
    u64 d; asm("fma.rn.f32x2 %0, %1, %2, %3;" : "=l"(d) : "l"(a), "l"(b), "l"(c));
    return d;
}
__device__ __forceinline__ float ex2f(float x) {
    float r; asm("ex2.approx.f32 %0, %1;" : "=f"(r) : "f"(x)); return r;
}

// Input t = z*log2e (scaling folded into weights).
// g = elu(z)+1 = ln2*max(t,0) + min(2^t, 1)
__device__ __forceinline__ u64 elu2g(u64 t) {
    float tl, th; unpack2(t, tl, th);
    float el = ex2f(tl), eh = ex2f(th);
    float rl = fmaf(0.69314718055994530942f, fmaxf(tl, 0.0f), fminf(el, 1.0f));
    float rh = fmaf(0.69314718055994530942f, fmaxf(th, 0.0f), fminf(eh, 1.0f));
    return pack2(rl, rh);
}

__global__ void __launch_bounds__(THREADS, 3)
net0_kernel(const float* __restrict__ x,
            const float* __restrict__ W1, const float* __restrict__ b1,
            const float* __restrict__ Wm, const float* __restrict__ bm,
            const float* __restrict__ Wo, const float* __restrict__ bo,
            float* __restrict__ out, int nQuads)
{
    __shared__ __align__(16) float2 sFc1[H * 4];         // per i: {w0d, w1d, bd, pad}  (x log2e)
    __shared__ __align__(16) float2 sMid[NMID * LSTRIDE];// (x log2e, bias -rowsum fold)
    __shared__ __align__(16) float2 sFcO[2 * 8];         // unscaled, bias -rowsum fold

    const float LOG2E = 1.44269504088896340736f;

    // fc1: scale W and b by log2e (input x is raw, no +1 fold on input side).
    for (int idx = threadIdx.x; idx < H * 4; idx += THREADS) {
        int i = idx >> 2, k = idx & 3;
        float v = (k < 2) ? W1[i * 2 + k] * LOG2E
                          : (k == 2 ? b1[i] * LOG2E : 0.0f);
        sFc1[idx] = make_float2(v, v);
    }
    // mid layers: b' = b - rowsum(W); then scale both W and b' by log2e.
    for (int idx = threadIdx.x; idx < NMID * H * 8; idx += THREADS) {
        int l = idx / (H * 8);
        int r = idx - l * (H * 8);
        int i = r >> 3, k = r & 7;
        float v;
        if (k < 7) {
            v = Wm[(l * H + i) * H + k] * LOG2E;
        } else {
            float s = 0.0f;
            for (int j = 0; j < H; j++) s += Wm[(l * H + i) * H + j];
            v = (bm[l * H + i] - s) * LOG2E;
        }
        sMid[l * LSTRIDE + i * 8 + k] = make_float2(v, v);
    }
    // fc21: unscaled (true logits), bias fold only: bo' = bo - rowsum(Wo).
    for (int idx = threadIdx.x; idx < 16; idx += THREADS) {
        int r = idx >> 3, k = idx & 7;
        float v;
        if (k < 7) {
            v = Wo[r * H + k];
        } else {
            float s = 0.0f;
            for (int j = 0; j < H; j++) s += Wo[r * H + j];
            v = bo[r] - s;
        }
        sFcO[idx] = make_float2(v, v);
    }
    __syncthreads();

    int q = blockIdx.x * THREADS + threadIdx.x;   // 4 rows per thread
    if (q >= nQuads) return;

    float4 xa = reinterpret_cast<const float4*>(x)[2 * q + 0];  // rows 4q,4q+1
    float4 xb = reinterpret_cast<const float4*>(x)[2 * q + 1];  // rows 4q+2,4q+3
    u64 xa0 = pack2(xa.x, xa.z), xa1 = pack2(xa.y, xa.w);
    u64 xb0 = pack2(xb.x, xb.z), xb1 = pack2(xb.y, xb.w);

    u64 ha[H], hb[H];   // carry g = elu(z)+1

    // ---- fc1 + ELU(g) ----
#pragma unroll
    for (int i = 0; i < H; i++) {
        const ulonglong2* p = reinterpret_cast<const ulonglong2*>(&sFc1[i * 4]);
        ulonglong2 a = p[0];      // {w0 dup, w1 dup}  (x log2e)
        ulonglong2 b = p[1];      // {bias dup, pad}   (x log2e)
        ha[i] = elu2g(fma2(a.x, xa0, fma2(a.y, xa1, b.x)));
        hb[i] = elu2g(fma2(a.x, xb0, fma2(a.y, xb1, b.x)));
    }

    // ---- fc2..fc20 : rolled layer loop ----
#pragma unroll 1
    for (int l = 0; l < NMID; l++) {
        const ulonglong2* base =
            reinterpret_cast<const ulonglong2*>(&sMid[l * LSTRIDE]);
        u64 hna[H], hnb[H];
#pragma unroll
        for (int i = 0; i < H; i++) {
            ulonglong2 q0 = base[i * 4 + 0];   // w0,w1
            ulonglong2 q1 = base[i * 4 + 1];   // w2,w3
            ulonglong2 q2 = base[i * 4 + 2];   // w4,w5
            ulonglong2 q3 = base[i * 4 + 3];   // w6,bias'
            u64 acca = q3.y, accb = q3.y;
            acca = fma2(q0.x, ha[0], acca);  accb = fma2(q0.x, hb[0], accb);
            acca = fma2(q0.y, ha[1], acca);  accb = fma2(q0.y, hb[1], accb);
            acca = fma2(q1.x, ha[2], acca);  accb = fma2(q1.x, hb[2], accb);
            acca = fma2(q1.y, ha[3], acca);  accb = fma2(q1.y, hb[3], accb);
            acca = fma2(q2.x, ha[4], acca);  accb = fma2(q2.x, hb[4], accb);
            acca = fma2(q2.y, ha[5], acca);  accb = fma2(q2.y, hb[5], accb);
            acca = fma2(q3.x, ha[6], acca);  accb = fma2(q3.x, hb[6], accb);
            hna[i] = acca;  hnb[i] = accb;
        }
#pragma unroll
        for (int i = 0; i < H; i++) {
            ha[i] = elu2g(hna[i]);
            hb[i] = elu2g(hnb[i]);
        }
    }

    // ---- fc21 (2 logits per row, adjusted bias, unscaled) ----
    u64 lpa[2], lpb[2];
#pragma unroll
    for (int r = 0; r < 2; r++) {
        const ulonglong2* p = reinterpret_cast<const ulonglong2*>(&sFcO[r * 8]);
        ulonglong2 q0 = p[0], q1 = p[1], q2 = p[2], q3 = p[3];
        u64 acca = q3.y, accb = q3.y;
        acca = fma2(q0.x, ha[0], acca);  accb = fma2(q0.x, hb[0], accb);
        acca = fma2(q0.y, ha[1], acca);  accb = fma2(q0.y, hb[1], accb);
        acca = fma2(q1.x, ha[2], acca);  accb = fma2(q1.x, hb[2], accb);
        acca = fma2(q1.y, ha[3], acca);  accb = fma2(q1.y, hb[3], accb);
        acca = fma2(q2.x, ha[4], acca);  accb = fma2(q2.x, hb[4], accb);
        acca = fma2(q2.y, ha[5], acca);  accb = fma2(q2.y, hb[5], accb);
        acca = fma2(q3.x, ha[6], acca);  accb = fma2(q3.x, hb[6], accb);
        lpa[r] = acca;  lpb[r] = accb;
    }

    float a0lo, a0hi, a1lo, a1hi, b0lo, b0hi, b1lo, b1hi;
    unpack2(lpa[0], a0lo, a0hi);  unpack2(lpa[1], a1lo, a1hi);
    unpack2(lpb[0], b0lo, b0hi);  unpack2(lpb[1], b1lo, b1hi);

    auto lsm = [](float l0, float l1, float& o0, float& o1) {
        float m   = fmaxf(l0, l1);
        float s   = ex2f((l0 - m) * 1.44269504088896340736f)
                  + ex2f((l1 - m) * 1.44269504088896340736f);
        float lse = m + __logf(s);
        o0 = l0 - lse;  o1 = l1 - lse;
    };

    float4 oa, ob;
    lsm(a0lo, a1lo, oa.x, oa.y);   // row 4q
    lsm(a0hi, a1hi, oa.z, oa.w);   // row 4q+1
    lsm(b0lo, b1lo, ob.x, ob.y);   // row 4q+2
    lsm(b0hi, b1hi, ob.z, ob.w);   // row 4q+3

    reinterpret_cast<float4*>(out)[2 * q + 0] = oa;
    reinterpret_cast<float4*>(out)[2 * q + 1] = ob;
}

extern "C" void kernel_launch(void* const* d_in, const int* in_sizes, int n_in,
                              void* d_out, int out_size)
{
    const float* x  = (const float*)d_in[0];
    const float* W1 = (const float*)d_in[1];
    const float* b1 = (const float*)d_in[2];
    const float* Wm = (const float*)d_in[3];
    const float* bm = (const float*)d_in[4];
    const float* Wo = (const float*)d_in[5];
    const float* bo = (const float*)d_in[6];
    float* out = (float*)d_out;

    int nQuads = in_sizes[0] / 8;   // x is [B,2]; 4 rows per thread
    int grid = (nQuads + THREADS - 1) / THREADS;
    net0_kernel<<<grid, THREADS>>>(x, W1, b1, Wm, bm, Wo, bo, out, nQuads);
}

// round 7
// speedup vs baseline: 1.0387x; 1.0387x over previous
#include <cuda_runtime.h>

// Net0: x[B,2] -> fc1(2,7)+ELU -> 19x fc(7,7)+ELU -> fc(7,2) -> log_softmax.
// R7 = R5 (best: 270us) + FULL UNROLL of the 19-layer loop:
//   - shared addresses become immediates (no per-layer IMAD/IADD/ISETP/BRA)
//   - ptxas schedules next layer's LDS under current layer's MUFU shadow.
// ELU carried as g = elu(z)+1 = fmax(z,0) + fmin(exp(z),1); the -1 folded
// into the next layer's bias (b' = b - rowsum(W)).

constexpr int H       = 7;
constexpr int NMID    = 19;
constexpr int THREADS = 256;
constexpr int LSTRIDE = 56;   // float2 slots per layer: 7 i * (7 w + 1 bias)

typedef unsigned long long u64;

__device__ __forceinline__ u64 pack2(float lo, float hi) {
    u64 r; asm("mov.b64 %0, {%1, %2};" : "=l"(r) : "f"(lo), "f"(hi)); return r;
}
__device__ __forceinline__ void unpack2(u64 v, float& lo, float& hi) {
    asm("mov.b64 {%0, %1}, %2;" : "=f"(lo), "=f"(hi) : "l"(v));
}
__device__ __forceinline__ u64 fma2(u64 a, u64 b, u64 c) {
    u64 d; asm("fma.rn.f32x2 %0, %1, %2, %3;" : "=l"(d) : "l"(a), "l"(b), "l"(c));
    return d;
}
__device__ __forceinline__ u64 mul2(u64 a, u64 b) {
    u64 d; asm("mul.rn.f32x2 %0, %1, %2;" : "=l"(d) : "l"(a), "l"(b)); return d;
}
__device__ __forceinline__ float ex2f(float x) {
    float r; asm("ex2.approx.f32 %0, %1;" : "=f"(r) : "f"(x)); return r;
}

// g = elu(z) + 1 = max(z,0) + min(exp(z),1).
__device__ __forceinline__ u64 elu2g(u64 z, u64 cLog2e) {
    u64 t = mul2(z, cLog2e);
    float tl, th; unpack2(t, tl, th);
    float el = ex2f(tl), eh = ex2f(th);
    float zl, zh; unpack2(z, zl, zh);
    float rl = fmaxf(zl, 0.0f) + fminf(el, 1.0f);
    float rh = fmaxf(zh, 0.0f) + fminf(eh, 1.0f);
    return pack2(rl, rh);
}

__global__ void __launch_bounds__(THREADS, 3)
net0_kernel(const float* __restrict__ x,
            const float* __restrict__ W1, const float* __restrict__ b1,
            const float* __restrict__ Wm, const float* __restrict__ bm,
            const float* __restrict__ Wo, const float* __restrict__ bo,
            float* __restrict__ out, int nQuads)
{
    __shared__ __align__(16) float2 sFc1[H * 4];         // per i: {w0d, w1d, bd, pad}
    __shared__ __align__(16) float2 sMid[NMID * LSTRIDE];
    __shared__ __align__(16) float2 sFcO[2 * 8];         // per r: 7 wd + bias' d

    // fc1: raw bias (its input x is not an ELU-g).
    for (int idx = threadIdx.x; idx < H * 4; idx += THREADS) {
        int i = idx >> 2, k = idx & 3;
        float v = (k < 2) ? W1[i * 2 + k] : (k == 2 ? b1[i] : 0.0f);
        sFc1[idx] = make_float2(v, v);
    }
    // mid layers: adjusted bias b' = b - rowsum(W) (consumes g = h+1).
    for (int idx = threadIdx.x; idx < NMID * H * 8; idx += THREADS) {
        int l = idx / (H * 8);
        int r = idx - l * (H * 8);
        int i = r >> 3, k = r & 7;
        float v;
        if (k < 7) {
            v = Wm[(l * H + i) * H + k];
        } else {
            float s = 0.0f;
            for (int j = 0; j < H; j++) s += Wm[(l * H + i) * H + j];
            v = bm[l * H + i] - s;
        }
        sMid[l * LSTRIDE + i * 8 + k] = make_float2(v, v);
    }
    // fc21: adjusted bias bo' = bo - rowsum(Wo).
    for (int idx = threadIdx.x; idx < 16; idx += THREADS) {
        int r = idx >> 3, k = idx & 7;
        float v;
        if (k < 7) {
            v = Wo[r * H + k];
        } else {
            float s = 0.0f;
            for (int j = 0; j < H; j++) s += Wo[r * H + j];
            v = bo[r] - s;
        }
        sFcO[idx] = make_float2(v, v);
    }
    __syncthreads();

    const u64 cLog2e = pack2(1.4426950408889634f, 1.4426950408889634f);

    int q = blockIdx.x * THREADS + threadIdx.x;   // 4 rows per thread
    if (q >= nQuads) return;

    float4 xa = reinterpret_cast<const float4*>(x)[2 * q + 0];  // rows 4q,4q+1
    float4 xb = reinterpret_cast<const float4*>(x)[2 * q + 1];  // rows 4q+2,4q+3
    u64 xa0 = pack2(xa.x, xa.z), xa1 = pack2(xa.y, xa.w);
    u64 xb0 = pack2(xb.x, xb.z), xb1 = pack2(xb.y, xb.w);

    u64 ha[H], hb[H];   // carry g = elu(z)+1

    // ---- fc1 + ELU(g) ----
#pragma unroll
    for (int i = 0; i < H; i++) {
        const ulonglong2* p = reinterpret_cast<const ulonglong2*>(&sFc1[i * 4]);
        ulonglong2 a = p[0];      // {w0 dup, w1 dup}
        ulonglong2 b = p[1];      // {bias dup, pad}
        ha[i] = elu2g(fma2(a.x, xa0, fma2(a.y, xa1, b.x)), cLog2e);
        hb[i] = elu2g(fma2(a.x, xb0, fma2(a.y, xb1, b.x)), cLog2e);
    }

    // ---- fc2..fc20 : FULLY UNROLLED layer loop (immediate LDS addressing,
    //      cross-layer instruction scheduling) ----
#pragma unroll
    for (int l = 0; l < NMID; l++) {
        const ulonglong2* base =
            reinterpret_cast<const ulonglong2*>(&sMid[l * LSTRIDE]);
        u64 hna[H], hnb[H];
#pragma unroll
        for (int i = 0; i < H; i++) {
            ulonglong2 q0 = base[i * 4 + 0];   // w0,w1
            ulonglong2 q1 = base[i * 4 + 1];   // w2,w3
            ulonglong2 q2 = base[i * 4 + 2];   // w4,w5
            ulonglong2 q3 = base[i * 4 + 3];   // w6,bias'
            u64 acca = q3.y, accb = q3.y;
            acca = fma2(q0.x, ha[0], acca);  accb = fma2(q0.x, hb[0], accb);
            acca = fma2(q0.y, ha[1], acca);  accb = fma2(q0.y, hb[1], accb);
            acca = fma2(q1.x, ha[2], acca);  accb = fma2(q1.x, hb[2], accb);
            acca = fma2(q1.y, ha[3], acca);  accb = fma2(q1.y, hb[3], accb);
            acca = fma2(q2.x, ha[4], acca);  accb = fma2(q2.x, hb[4], accb);
            acca = fma2(q2.y, ha[5], acca);  accb = fma2(q2.y, hb[5], accb);
            acca = fma2(q3.x, ha[6], acca);  accb = fma2(q3.x, hb[6], accb);
            hna[i] = acca;  hnb[i] = accb;
        }
#pragma unroll
        for (int i = 0; i < H; i++) {
            ha[i] = elu2g(hna[i], cLog2e);
            hb[i] = elu2g(hnb[i], cLog2e);
        }
    }

    // ---- fc21 (2 logits per row, adjusted bias) ----
    u64 lpa[2], lpb[2];
#pragma unroll
    for (int r = 0; r < 2; r++) {
        const ulonglong2* p = reinterpret_cast<const ulonglong2*>(&sFcO[r * 8]);
        ulonglong2 q0 = p[0], q1 = p[1], q2 = p[2], q3 = p[3];
        u64 acca = q3.y, accb = q3.y;
        acca = fma2(q0.x, ha[0], acca);  accb = fma2(q0.x, hb[0], accb);
        acca = fma2(q0.y, ha[1], acca);  accb = fma2(q0.y, hb[1], accb);
        acca = fma2(q1.x, ha[2], acca);  accb = fma2(q1.x, hb[2], accb);
        acca = fma2(q1.y, ha[3], acca);  accb = fma2(q1.y, hb[3], accb);
        acca = fma2(q2.x, ha[4], acca);  accb = fma2(q2.x, hb[4], accb);
        acca = fma2(q2.y, ha[5], acca);  accb = fma2(q2.y, hb[5], accb);
        acca = fma2(q3.x, ha[6], acca);  accb = fma2(q3.x, hb[6], accb);
        lpa[r] = acca;  lpb[r] = accb;
    }

    float a0lo, a0hi, a1lo, a1hi, b0lo, b0hi, b1lo, b1hi;
    unpack2(lpa[0], a0lo, a0hi);  unpack2(lpa[1], a1lo, a1hi);
    unpack2(lpb[0], b0lo, b0hi);  unpack2(lpb[1], b1lo, b1hi);

    auto lsm = [](float l0, float l1, float& o0, float& o1) {
        float m   = fmaxf(l0, l1);
        float s   = ex2f((l0 - m) * 1.4426950408889634f)
                  + ex2f((l1 - m) * 1.4426950408889634f);
        float lse = m + __logf(s);
        o0 = l0 - lse;  o1 = l1 - lse;
    };

    float4 oa, ob;
    lsm(a0lo, a1lo, oa.x, oa.y);   // row 4q
    lsm(a0hi, a1hi, oa.z, oa.w);   // row 4q+1
    lsm(b0lo, b1lo, ob.x, ob.y);   // row 4q+2
    lsm(b0hi, b1hi, ob.z, ob.w);   // row 4q+3

    reinterpret_cast<float4*>(out)[2 * q + 0] = oa;
    reinterpret_cast<float4*>(out)[2 * q + 1] = ob;
}

extern "C" void kernel_launch(void* const* d_in, const int* in_sizes, int n_in,
                              void* d_out, int out_size)
{
    const float* x  = (const float*)d_in[0];
    const float* W1 = (const float*)d_in[1];
    const float* b1 = (const float*)d_in[2];
    const float* Wm = (const float*)d_in[3];
    const float* bm = (const float*)d_in[4];
    const float* Wo = (const float*)d_in[5];
    const float* bo = (const float*)d_in[6];
    float* out = (float*)d_out;

    int nQuads = in_sizes[0] / 8;   // x is [B,2]; 4 rows per thread
    int grid = (nQuads + THREADS - 1) / THREADS;
    net0_kernel<<<grid, THREADS>>>(x, W1, b1, Wm, bm, Wo, bo, out, nQuads);
}